// round 4
// baseline (speedup 1.0000x reference)
#include <cuda_runtime.h>

#define NROWS   512      // 16 * 32
#define NP      256      // particles per row
#define OD      10       // OBS_DIM
#define AD      4        // ACTION_DIM
#define ROW_LEN 2564
#define NBLK    1024     // (row, dir) blocks

__device__ float g_partial[NBLK];
__device__ float g_action[NROWS];
__device__ float g_a0[NROWS];
__device__ int   g_cnt;          // zero-init; last block resets it each run

typedef unsigned long long ull;

__device__ __forceinline__ ull pk2(float a, float b) {
    ull r; asm("mov.b64 %0, {%1, %2};" : "=l"(r) : "f"(a), "f"(b)); return r;
}
__device__ __forceinline__ ull add2_(ull a, ull b) {
    ull r; asm("add.rn.f32x2 %0, %1, %2;" : "=l"(r) : "l"(a), "l"(b)); return r;
}
__device__ __forceinline__ ull fma2_(ull a, ull b, ull c) {
    ull r; asm("fma.rn.f32x2 %0, %1, %2, %3;" : "=l"(r) : "l"(a), "l"(b), "l"(c)); return r;
}
__device__ __forceinline__ unsigned umin_(unsigned a, unsigned b) { return a < b ? a : b; }

__global__ __launch_bounds__(128, 10)
void chamfer_kernel(const float* __restrict__ preds,
                    const float* __restrict__ targ,
                    float* __restrict__ out) {
    const int blk = blockIdx.x;
    const int r   = blk >> 1;        // row = b*32 + h
    const int dir = blk & 1;         // 0: scan obs / query targ (idx1), 1: scan targ / query obs (idx2)
    const int t   = threadIdx.x;

    // scan side: staged in smem (argmin target + gather source, random access)
    // mine side: read directly from global (thread-private columns)
    const float* __restrict__ scan_g = (dir ? targ : preds) + (size_t)r * ROW_LEN + AD;
    const float* __restrict__ mine_g = (dir ? preds : targ) + (size_t)r * ROW_LEN + AD;

    __shared__ float scan_s[NP * OD];       // 10 KB
    __shared__ ulonglong2 sxy[NP / 2];      // packed (x-pair, y-pair)  2 KB
    __shared__ ulonglong2 szw[NP / 2];      // packed (z-pair, w-pair)  2 KB
    __shared__ ull        shn[NP / 2];      // packed half-norm pairs   1 KB
    __shared__ float red[128];
    __shared__ int s_last;

    // ---- stage scan rows (float4: base (r*2564+4)*4 is 16B-aligned) ----
    #pragma unroll
    for (int i = t; i < NP * OD / 4; i += 128)
        ((float4*)scan_s)[i] = ((const float4*)scan_g)[i];
    __syncthreads();

    // ---- pack scan-side features (dims 5..8) as f32x2 pairs + half-norms ----
    {
        const int k0 = 2 * t, k1 = 2 * t + 1;
        float x0 = scan_s[k0*OD+5], y0 = scan_s[k0*OD+6], z0 = scan_s[k0*OD+7], w0 = scan_s[k0*OD+8];
        float x1 = scan_s[k1*OD+5], y1 = scan_s[k1*OD+6], z1 = scan_s[k1*OD+7], w1 = scan_s[k1*OD+8];
        sxy[t] = make_ulonglong2(pk2(x0, x1), pk2(y0, y1));
        szw[t] = make_ulonglong2(pk2(z0, z1), pk2(w0, w1));
        shn[t] = pk2(0.5f * (x0*x0 + y0*y0 + z0*z0 + w0*w0),
                     0.5f * (x1*x1 + y1*y1 + z1*z1 + w1*w1));
    }
    __syncthreads();

    // ---- per-thread query columns: adjacent for cache locality ----
    const int cA = 2 * t, cB = 2 * t + 1;
    const float ax = __ldg(mine_g + cA*OD+5), ay = __ldg(mine_g + cA*OD+6);
    const float az = __ldg(mine_g + cA*OD+7), aw = __ldg(mine_g + cA*OD+8);
    const float bx = __ldg(mine_g + cB*OD+5), by = __ldg(mine_g + cB*OD+6);
    const float bz = __ldg(mine_g + cB*OD+7), bw = __ldg(mine_g + cB*OD+8);
    const ull nAx = pk2(-ax, -ax), nAy = pk2(-ay, -ay), nAz = pk2(-az, -az), nAw = pk2(-aw, -aw);
    const ull nBx = pk2(-bx, -bx), nBy = pk2(-by, -by), nBz = pk2(-bz, -bz), nBw = pk2(-bw, -bw);
    const float hA = 1.0f + 0.5f * (ax*ax + ay*ay + az*az + aw*aw);
    const float hB = 1.0f + 0.5f * (bx*bx + by*by + bz*bz + bw*bw);
    const ull baseA = pk2(hA, hA);
    const ull baseB = pk2(hB, hB);

    // score = 1 + half|s|^2 + half|q|^2 - s.q  (monotone in sq-distance, >= 1 -> sign bit 0)
    // key = (score_bits & ~0xFF) | k  -> unsigned min = first-occurrence argmin
    unsigned bestA = 0xFFFFFFFFu, bestB = 0xFFFFFFFFu;
    #pragma unroll 2
    for (int kk = 0; kk < NP / 2; ++kk) {
        const ulonglong2 xy = sxy[kk];
        const ulonglong2 zw = szw[kk];
        const ull h2 = shn[kk];

        ull sA = add2_(h2, baseA);
        sA = fma2_(xy.x, nAx, sA);
        sA = fma2_(xy.y, nAy, sA);
        sA = fma2_(zw.x, nAz, sA);
        sA = fma2_(zw.y, nAw, sA);

        ull sB = add2_(h2, baseB);
        sB = fma2_(xy.x, nBx, sB);
        sB = fma2_(xy.y, nBy, sB);
        sB = fma2_(zw.x, nBz, sB);
        sB = fma2_(zw.y, nBw, sB);

        const unsigned k0 = 2u * kk, k1 = 2u * kk + 1u;
        bestA = umin_(bestA, ((unsigned)sA         & 0xFFFFFF00u) | k0);
        bestA = umin_(bestA, ((unsigned)(sA >> 32) & 0xFFFFFF00u) | k1);
        bestB = umin_(bestB, ((unsigned)sB         & 0xFFFFFF00u) | k0);
        bestB = umin_(bestB, ((unsigned)(sB >> 32) & 0xFFFFFF00u) | k1);
    }

    const int iA = bestA & 0xFF;
    const int iB = bestB & 0xFF;

    // ---- L1 gather over all 10 dims: scan row from smem, query row from global ----
    float s1 = 0.f, s2 = 0.f;
    #pragma unroll
    for (int d = 0; d < OD; ++d) {
        s1 += fabsf(scan_s[iA * OD + d] - __ldg(mine_g + cA * OD + d));
        s2 += fabsf(scan_s[iB * OD + d] - __ldg(mine_g + cB * OD + d));
    }
    const float w = dir ? 1.0f : 3.0f;   // TARGET_WEIGHT on the idx1 direction
    red[t] = w * (s1 + s2);
    __syncthreads();
    #pragma unroll
    for (int off = 64; off > 0; off >>= 1) {
        if (t < off) red[t] += red[t + off];
        __syncthreads();
    }

    if (t == 0) {
        g_partial[blk] = red[0];
        if (dir == 0) {
            const float* pr = preds + (size_t)r * ROW_LEN;
            const float* tg = targ  + (size_t)r * ROW_LEN;
            float al1 = 0.f;
            #pragma unroll
            for (int d = 0; d < AD; ++d) al1 += fabsf(pr[d] - tg[d]);
            al1 *= 0.25f;
            const int h = r & 31;
            g_action[r] = (h == 1) ? al1 * 10.0f : al1;
            g_a0[r]     = (h == 1) ? al1 : 0.0f;
        }
        __threadfence();
        const int ticket = atomicAdd(&g_cnt, 1);
        s_last = (ticket == NBLK - 1) ? 1 : 0;
    }
    __syncthreads();

    // ---- fused final reduction: last block to finish does it ----
    if (s_last) {
        float c = 0.f;
        for (int i = t; i < NBLK; i += 128) c += g_partial[i];
        red[t] = c;
        __syncthreads();
        #pragma unroll
        for (int off = 64; off > 0; off >>= 1) {
            if (t < off) red[t] += red[t + off];
            __syncthreads();
        }
        const float chamfer_total = red[0];
        __syncthreads();

        float a = 0.f;
        for (int i = t; i < NROWS; i += 128) a += g_action[i];
        red[t] = a;
        __syncthreads();
        #pragma unroll
        for (int off = 64; off > 0; off >>= 1) {
            if (t < off) red[t] += red[t + off];
            __syncthreads();
        }
        const float action_total = red[0];
        __syncthreads();

        float z = 0.f;
        for (int i = t; i < NROWS; i += 128) z += g_a0[i];
        red[t] = z;
        __syncthreads();
        #pragma unroll
        for (int off = 64; off > 0; off >>= 1) {
            if (t < off) red[t] += red[t + off];
            __syncthreads();
        }
        const float a0_total = red[0];

        if (t == 0) {
            // chamfer mean = total / (4 * 512*256*10)
            out[0] = action_total * (1.0f / NROWS) + chamfer_total * (1.0f / 5242880.0f);
            out[1] = a0_total * (1.0f / 16.0f);
            g_cnt  = 0;   // reset for next graph replay
        }
    }
}

extern "C" void kernel_launch(void* const* d_in, const int* in_sizes, int n_in,
                              void* d_out, int out_size) {
    const float* preds = (const float*)d_in[0];
    const float* targ  = (const float*)d_in[1];
    chamfer_kernel<<<NBLK, 128>>>(preds, targ, (float*)d_out);
}

// round 6
// speedup vs baseline: 1.5122x; 1.5122x over previous
#include <cuda_runtime.h>

#define NROWS   512      // 16 * 32
#define NP      256      // particles per row
#define OD      10       // OBS_DIM
#define AD      4        // ACTION_DIM
#define ROW_LEN 2564
#define NBLK    1024     // (row, dir) blocks

__device__ float g_partial[NBLK];
__device__ float g_action[NROWS];
__device__ float g_a0[NROWS];
__device__ int   g_cnt;          // zero-init; last block resets it each run

typedef unsigned long long ull;

__device__ __forceinline__ ull pk2(float a, float b) {
    ull r; asm("mov.b64 %0, {%1, %2};" : "=l"(r) : "f"(a), "f"(b)); return r;
}
__device__ __forceinline__ ull add2_(ull a, ull b) {
    ull r; asm("add.rn.f32x2 %0, %1, %2;" : "=l"(r) : "l"(a), "l"(b)); return r;
}
__device__ __forceinline__ ull fma2_(ull a, ull b, ull c) {
    ull r; asm("fma.rn.f32x2 %0, %1, %2, %3;" : "=l"(r) : "l"(a), "l"(b), "l"(c)); return r;
}
__device__ __forceinline__ unsigned umin_(unsigned a, unsigned b) { return a < b ? a : b; }

__global__ __launch_bounds__(256, 7)
void chamfer_kernel(const float* __restrict__ preds,
                    const float* __restrict__ targ,
                    float* __restrict__ out) {
    const int blk = blockIdx.x;
    const int r   = blk >> 1;        // row = b*32 + h
    const int dir = blk & 1;         // 0: scan obs / query targ (idx1, w=3), 1: scan targ / query obs
    const int t   = threadIdx.x;     // query column q = t  (0..255)

    __shared__ float obs_s[NP * OD];        // 10 KB
    __shared__ float obt_s[NP * OD];        // 10 KB
    __shared__ ulonglong2 sxy[NP / 2];      // packed (x-pair, y-pair)  2 KB
    __shared__ ulonglong2 szw[NP / 2];      // packed (z-pair, w-pair)  2 KB
    __shared__ ull        shn[NP / 2];      // packed half-norm pairs   1 KB
    __shared__ float red[256];
    __shared__ int s_last;

    // ---- stage both rows (float4: base (r*2564+4)*4 is 16B-aligned) ----
    const float4* pr4 = (const float4*)(preds + (size_t)r * ROW_LEN + AD);
    const float4* tg4 = (const float4*)(targ  + (size_t)r * ROW_LEN + AD);
    #pragma unroll
    for (int i = t; i < NP * OD / 4; i += 256) {
        ((float4*)obs_s)[i] = pr4[i];
        ((float4*)obt_s)[i] = tg4[i];
    }
    __syncthreads();

    const float* scan = dir ? obt_s : obs_s;   // side we argmin over (candidates)
    const float* mine = dir ? obs_s : obt_s;   // side providing the query column

    // ---- pack candidate features (dims 5..8) as f32x2 pairs + half-norms ----
    if (t < NP / 2) {
        const int k0 = 2 * t, k1 = 2 * t + 1;
        float x0 = scan[k0*OD+5], y0 = scan[k0*OD+6], z0 = scan[k0*OD+7], w0 = scan[k0*OD+8];
        float x1 = scan[k1*OD+5], y1 = scan[k1*OD+6], z1 = scan[k1*OD+7], w1 = scan[k1*OD+8];
        sxy[t] = make_ulonglong2(pk2(x0, x1), pk2(y0, y1));
        szw[t] = make_ulonglong2(pk2(z0, z1), pk2(w0, w1));
        shn[t] = pk2(0.5f * (x0*x0 + y0*y0 + z0*z0 + w0*w0),
                     0.5f * (x1*x1 + y1*y1 + z1*z1 + w1*w1));
    }
    __syncthreads();

    // ---- this thread's query features ----
    const float ax = mine[t*OD+5], ay = mine[t*OD+6], az = mine[t*OD+7], aw = mine[t*OD+8];
    const ull nAx = pk2(-ax, -ax), nAy = pk2(-ay, -ay), nAz = pk2(-az, -az), nAw = pk2(-aw, -aw);
    const float hA = 1.0f + 0.5f * (ax*ax + ay*ay + az*az + aw*aw);
    const ull baseA = pk2(hA, hA);

    // score = 1 + half|s|^2 + half|q|^2 - s.q  (monotone in sq-dist, >= ~1 -> sign bit 0)
    // key = (score_bits & ~0xFF) | k  -> unsigned min = first-occurrence argmin
    unsigned bestA = 0xFFFFFFFFu;
    #pragma unroll 4
    for (int kk = 0; kk < NP / 2; ++kk) {
        const ulonglong2 xy = sxy[kk];
        const ulonglong2 zw = szw[kk];
        const ull h2 = shn[kk];

        ull sA = add2_(h2, baseA);
        sA = fma2_(xy.x, nAx, sA);
        sA = fma2_(xy.y, nAy, sA);
        sA = fma2_(zw.x, nAz, sA);
        sA = fma2_(zw.y, nAw, sA);

        const unsigned k0 = 2u * kk, k1 = 2u * kk + 1u;
        bestA = umin_(bestA, ((unsigned)sA         & 0xFFFFFF00u) | k0);
        bestA = umin_(bestA, ((unsigned)(sA >> 32) & 0xFFFFFF00u) | k1);
    }
    const int iA = bestA & 0xFF;

    // ---- L1 gather over all 10 dims (both rows in smem) ----
    float s1 = 0.f;
    #pragma unroll
    for (int d = 0; d < OD; ++d)
        s1 += fabsf(scan[iA * OD + d] - mine[t * OD + d]);
    const float w = dir ? 1.0f : 3.0f;   // TARGET_WEIGHT on the idx1 direction
    red[t] = w * s1;
    __syncthreads();
    #pragma unroll
    for (int off = 128; off > 0; off >>= 1) {
        if (t < off) red[t] += red[t + off];
        __syncthreads();
    }

    if (t == 0) {
        g_partial[blk] = red[0];
        if (dir == 0) {
            const float* pr = preds + (size_t)r * ROW_LEN;
            const float* tg = targ  + (size_t)r * ROW_LEN;
            float al1 = 0.f;
            #pragma unroll
            for (int d = 0; d < AD; ++d) al1 += fabsf(pr[d] - tg[d]);
            al1 *= 0.25f;
            const int h = r & 31;
            g_action[r] = (h == 1) ? al1 * 10.0f : al1;
            g_a0[r]     = (h == 1) ? al1 : 0.0f;
        }
        __threadfence();
        const int ticket = atomicAdd(&g_cnt, 1);
        s_last = (ticket == NBLK - 1) ? 1 : 0;
    }
    __syncthreads();

    // ---- fused final reduction: last block to finish does it ----
    if (s_last) {
        float c = 0.f;
        for (int i = t; i < NBLK; i += 256) c += g_partial[i];
        red[t] = c;
        __syncthreads();
        #pragma unroll
        for (int off = 128; off > 0; off >>= 1) {
            if (t < off) red[t] += red[t + off];
            __syncthreads();
        }
        const float chamfer_total = red[0];
        __syncthreads();

        float a = (t < NROWS) ? g_action[t] + g_action[t + 256] : 0.f;
        red[t] = a;
        __syncthreads();
        #pragma unroll
        for (int off = 128; off > 0; off >>= 1) {
            if (t < off) red[t] += red[t + off];
            __syncthreads();
        }
        const float action_total = red[0];
        __syncthreads();

        float z = (t < NROWS) ? g_a0[t] + g_a0[t + 256] : 0.f;
        red[t] = z;
        __syncthreads();
        #pragma unroll
        for (int off = 128; off > 0; off >>= 1) {
            if (t < off) red[t] += red[t + off];
            __syncthreads();
        }
        const float a0_total = red[0];

        if (t == 0) {
            // chamfer mean = total / (4 * 512*256*10)
            out[0] = action_total * (1.0f / NROWS) + chamfer_total * (1.0f / 5242880.0f);
            out[1] = a0_total * (1.0f / 16.0f);
            g_cnt  = 0;   // reset for next graph replay
        }
    }
}

extern "C" void kernel_launch(void* const* d_in, const int* in_sizes, int n_in,
                              void* d_out, int out_size) {
    const float* preds = (const float*)d_in[0];
    const float* targ  = (const float*)d_in[1];
    chamfer_kernel<<<NBLK, 256>>>(preds, targ, (float*)d_out);
}